// round 17
// baseline (speedup 1.0000x reference)
#include <cuda_runtime.h>
#include <cuda_fp16.h>
#include <cstdint>
#include <cstddef>

#define N_NODES 100000
#define FANOUT  16

// Global scratch (fp16)
__device__ __align__(16) __half g_SP[(size_t)N_NODES * 256];
__device__ __align__(16) __half g_Ah[(size_t)N_NODES * 256];
__device__ __align__(16) __half g_Hm[(size_t)N_NODES * 128];
// Packed weights (B layout), single fp16
#define WOFF1 0
#define WOFF2 65536
#define WOFF3 98304
#define WOFF4 131072
#define WTOT  147456
__device__ __align__(16) __half g_Bw[WTOT];

// ---------------------------------------------------------------------------
// Helpers
// ---------------------------------------------------------------------------
__device__ __forceinline__ uint32_t smem_u32(const void* p) {
    return (uint32_t)__cvta_generic_to_shared(p);
}
__device__ __forceinline__ void cp16(uint32_t dst, const void* src, int sz) {
    asm volatile("cp.async.cg.shared.global [%0], [%1], 16, %2;\n"
                 :: "r"(dst), "l"(src), "r"(sz));
}
__device__ __forceinline__ void ldsm_x4(uint32_t& r0, uint32_t& r1, uint32_t& r2,
                                        uint32_t& r3, uint32_t addr) {
    asm volatile("ldmatrix.sync.aligned.m8n8.x4.shared.b16 {%0,%1,%2,%3}, [%4];"
                 : "=r"(r0), "=r"(r1), "=r"(r2), "=r"(r3) : "r"(addr));
}
__device__ __forceinline__ void mma16816(float c[4], const uint32_t a[4], const uint32_t b[2]) {
    asm volatile(
        "mma.sync.aligned.m16n8k16.row.col.f32.f16.f16.f32 "
        "{%0,%1,%2,%3}, {%4,%5,%6,%7}, {%8,%9}, {%0,%1,%2,%3};\n"
        : "+f"(c[0]), "+f"(c[1]), "+f"(c[2]), "+f"(c[3])
        : "r"(a[0]), "r"(a[1]), "r"(a[2]), "r"(a[3]), "r"(b[0]), "r"(b[1]));
}
__device__ __forceinline__ __half2 u2h(uint32_t u) { return *(__half2*)&u; }

// ---------------------------------------------------------------------------
// fp16 tensor GEMM: C = act( A @ B^T )
// SPLITA: A k-cols [0,K/2) from A, [K/2,K) from A2 (both row stride 128).
// BM=128, BN=128, BK=64; 3-stage cp.async pipeline; SW128-swizzled 128B rows.
// ---------------------------------------------------------------------------
template<int K, int NT, bool RELU, bool SPLITA>
__global__ __launch_bounds__(256, 2)
void gemm_mma(const __half* __restrict__ A, const __half* __restrict__ A2,
              const __half* __restrict__ B, __half* __restrict__ C, int M) {
    constexpr int NC    = K / 64;
    constexpr int TSZ   = 128 * 128;
    constexpr int STAGE = 2 * TSZ;
    constexpr int AST   = SPLITA ? 128 : K;

    extern __shared__ char dsm[];
    const uint32_t base = (smem_u32(dsm) + 127u) & ~127u;

    const int tid  = threadIdx.x;
    const int wid  = tid >> 5;
    const int lane = tid & 31;
    const int g    = lane >> 2;
    const int tig  = lane & 3;
    const int wm   = wid & 1;
    const int wn   = wid >> 1;
    const int m0   = blockIdx.x * 128;

    const __half* Bp = B + (size_t)blockIdx.y * 128 * K;

    const int arow_add = ((lane >> 3) & 1) * 8;
    const int acol_g   = (lane >> 4) & 1;
    const int brow_add = ((lane >> 4) & 1) * 8;
    const int bcol_g   = (lane >> 3) & 1;

    uint32_t abase[4], axor[4];
    #pragma unroll
    for (int mi = 0; mi < 4; mi++) {
        int r = wm * 64 + mi * 16 + arow_add + (lane & 7);
        abase[mi] = r * 128;
        axor[mi]  = r & 7;
    }
    uint32_t bbase[2], bxor[2];
    #pragma unroll
    for (int np = 0; np < 2; np++) {
        int r = wn * 32 + np * 16 + brow_add + (lane & 7);
        bbase[np] = r * 128;
        bxor[np]  = r & 7;
    }

    auto load_chunk = [&](int kc, int s) {
        const uint32_t sb = base + s * STAGE;
        const __half* Asrc = (SPLITA && kc >= NC / 2) ? A2 : A;
        const int acol = SPLITA ? ((kc & (NC / 2 - 1)) * 64) : kc * 64;
        #pragma unroll
        for (int u = tid; u < 1024; u += 256) {
            int row = u >> 3, c16 = u & 7;
            uint32_t off = row * 128 + ((c16 ^ (row & 7)) << 4);
            int gr = m0 + row;
            int szA = (gr < M) ? 16 : 0;
            cp16(sb + off,       Asrc + (size_t)gr * AST + acol + c16 * 8, szA);
            cp16(sb + TSZ + off, Bp + (size_t)row * K + kc * 64 + c16 * 8, 16);
        }
        asm volatile("cp.async.commit_group;" ::: "memory");
    };

    float acc[4][4][4] = {};

    load_chunk(0, 0);
    if (NC > 1) load_chunk(1, 1);

    #pragma unroll
    for (int kc = 0; kc < NC; kc++) {
        const int s = kc % 3;
        if (kc + 1 < NC) asm volatile("cp.async.wait_group 1;" ::: "memory");
        else             asm volatile("cp.async.wait_group 0;" ::: "memory");
        __syncthreads();
        if (kc + 2 < NC) load_chunk(kc + 2, (kc + 2) % 3);

        const uint32_t sA = base + s * STAGE;
        const uint32_t sB = sA + TSZ;

        #pragma unroll
        for (int ks = 0; ks < 4; ks++) {
            uint32_t bh[4][2];
            #pragma unroll
            for (int np = 0; np < 2; np++) {
                uint32_t c = (uint32_t)(ks * 2 + bcol_g);
                uint32_t off = bbase[np] + ((c ^ bxor[np]) << 4);
                ldsm_x4(bh[np*2][0], bh[np*2][1], bh[np*2+1][0], bh[np*2+1][1], sB + off);
            }
            #pragma unroll
            for (int mi = 0; mi < 4; mi++) {
                uint32_t c = (uint32_t)(ks * 2 + acol_g);
                uint32_t off = abase[mi] + ((c ^ axor[mi]) << 4);
                uint32_t ah[4];
                ldsm_x4(ah[0], ah[1], ah[2], ah[3], sA + off);
                #pragma unroll
                for (int ni = 0; ni < 4; ni++)
                    mma16816(acc[mi][ni], ah, bh[ni]);
            }
        }
    }

    // Epilogue
    const int colbase = blockIdx.y * 128 + wn * 32;
    #pragma unroll
    for (int mi = 0; mi < 4; mi++) {
        int r0 = m0 + wm * 64 + mi * 16 + g;
        #pragma unroll
        for (int ni = 0; ni < 4; ni++) {
            int c = colbase + ni * 8 + tig * 2;
            float v0 = acc[mi][ni][0], v1 = acc[mi][ni][1];
            float v2 = acc[mi][ni][2], v3 = acc[mi][ni][3];
            if (RELU) {
                v0 = fmaxf(v0, 0.f); v1 = fmaxf(v1, 0.f);
                v2 = fmaxf(v2, 0.f); v3 = fmaxf(v3, 0.f);
            }
            if (r0 < M)
                *(__half2*)(C + (size_t)r0 * NT + c) = __floats2half2_rn(v0, v1);
            if (r0 + 8 < M)
                *(__half2*)(C + (size_t)(r0 + 8) * NT + c) = __floats2half2_rn(v2, v3);
        }
    }
}

// ---------------------------------------------------------------------------
// Converters
// ---------------------------------------------------------------------------
__global__ void conv_feat(const float* __restrict__ F, __half* __restrict__ Ah, int n4) {
    int i = blockIdx.x * 256 + threadIdx.x;
    if (i >= n4) return;
    float4 v = ((const float4*)F)[i];
    __half2 h0 = __floats2half2_rn(v.x, v.y);
    __half2 h1 = __floats2half2_rn(v.z, v.w);
    *(uint2*)(Ah + (size_t)i * 4) = make_uint2(*(uint32_t*)&h0, *(uint32_t*)&h1);
}

__global__ void conv_w_all(const float* __restrict__ W1, const float* __restrict__ W2,
                           const float* __restrict__ W3, const float* __restrict__ W4,
                           __half* __restrict__ bw) {
    int i = blockIdx.x * 256 + threadIdx.x;
    if (i >= WTOT) return;
    float v;
    if (i < WOFF2) {                 // L1: stacked [Ws1; Wn1], K=256
        int t = i, j = t >> 8, k = t & 255;
        v = (j < 128) ? W1[(size_t)j * 512 + k] : W1[(size_t)(j - 128) * 512 + 256 + k];
    } else if (i < WOFF3) {          // L2: identity [128, 256]
        v = W2[i - WOFF2];
    } else if (i < WOFF4) {          // L3: identity
        v = W3[i - WOFF3];
    } else {                         // L4: stacked [Ws4; Wn4], K=128
        int t = i - WOFF4, j = t >> 7, k = t & 127;
        v = (j < 64) ? W4[(size_t)j * 256 + k] : W4[(size_t)(j - 64) * 256 + 128 + k];
    }
    bw[i] = __float2half_rn(v);
}

// ---------------------------------------------------------------------------
// Gather kernels: HALF-WARP per row (2 rows per warp).
// Lanes 0-15 -> row 2*warp, lanes 16-31 -> row 2*warp+1.
// One LDG.128 per half-lane covers a full 256B row per half-warp.
// ---------------------------------------------------------------------------

// mean_h: Hm[w,:] = (1/16) * sum_j H[neigh[w][j], :]   (H rows: 128 halves)
__global__ void mean_h(const __half* __restrict__ H, const int* __restrict__ neigh,
                       __half* __restrict__ Hm, int M) {
    const int warp = (blockIdx.x * blockDim.x + threadIdx.x) >> 5;
    const int lane = threadIdx.x & 31;
    const int half = lane >> 4;
    const int hl   = lane & 15;
    const int w    = warp * 2 + half;
    const int wr   = (w < M) ? w : (M - 1);

    const int nid = neigh[(size_t)wr * FANOUT + hl];   // 16 lanes = FANOUT

    float acc[8] = {};
    #pragma unroll
    for (int p = 0; p < 8; p++) {
        int nj0 = __shfl_sync(0xffffffffu, nid, half * 16 + p);
        int nj1 = __shfl_sync(0xffffffffu, nid, half * 16 + p + 8);
        uint4 a = *(const uint4*)(H + (size_t)nj0 * 128 + hl * 8);
        uint4 b = *(const uint4*)(H + (size_t)nj1 * 128 + hl * 8);
        __half2 s0 = __hadd2(u2h(a.x), u2h(b.x));
        __half2 s1 = __hadd2(u2h(a.y), u2h(b.y));
        __half2 s2 = __hadd2(u2h(a.z), u2h(b.z));
        __half2 s3 = __hadd2(u2h(a.w), u2h(b.w));
        float2 f0 = __half22float2(s0), f1 = __half22float2(s1);
        float2 f2 = __half22float2(s2), f3 = __half22float2(s3);
        acc[0] += f0.x; acc[1] += f0.y; acc[2] += f1.x; acc[3] += f1.y;
        acc[4] += f2.x; acc[5] += f2.y; acc[6] += f3.x; acc[7] += f3.y;
    }
    if (w < M) {
        const float inv = 1.0f / (float)FANOUT;
        __half2 o0 = __floats2half2_rn(acc[0] * inv, acc[1] * inv);
        __half2 o1 = __floats2half2_rn(acc[2] * inv, acc[3] * inv);
        __half2 o2 = __floats2half2_rn(acc[4] * inv, acc[5] * inv);
        __half2 o3 = __floats2half2_rn(acc[6] * inv, acc[7] * inv);
        uint4 o = make_uint4(*(uint32_t*)&o0, *(uint32_t*)&o1,
                             *(uint32_t*)&o2, *(uint32_t*)&o3);
        *(uint4*)(Hm + (size_t)w * 128 + hl * 8) = o;
    }
}

// agg_split (L1): relu(S + mean(P)) -> fp16 h (row stride 128); SP [M,256]
__global__ void agg_split(const __half* __restrict__ SP, const int* __restrict__ neigh,
                          __half* __restrict__ H, int M) {
    const int warp = (blockIdx.x * blockDim.x + threadIdx.x) >> 5;
    const int lane = threadIdx.x & 31;
    const int half = lane >> 4;
    const int hl   = lane & 15;
    const int w    = warp * 2 + half;
    const int wr   = (w < M) ? w : (M - 1);

    const int nid = neigh[(size_t)wr * FANOUT + hl];

    float acc[8] = {};
    #pragma unroll
    for (int p = 0; p < 8; p++) {
        int nj0 = __shfl_sync(0xffffffffu, nid, half * 16 + p);
        int nj1 = __shfl_sync(0xffffffffu, nid, half * 16 + p + 8);
        uint4 a = *(const uint4*)(SP + (size_t)nj0 * 256 + 128 + hl * 8);
        uint4 b = *(const uint4*)(SP + (size_t)nj1 * 256 + 128 + hl * 8);
        __half2 s0 = __hadd2(u2h(a.x), u2h(b.x));
        __half2 s1 = __hadd2(u2h(a.y), u2h(b.y));
        __half2 s2 = __hadd2(u2h(a.z), u2h(b.z));
        __half2 s3 = __hadd2(u2h(a.w), u2h(b.w));
        float2 f0 = __half22float2(s0), f1 = __half22float2(s1);
        float2 f2 = __half22float2(s2), f3 = __half22float2(s3);
        acc[0] += f0.x; acc[1] += f0.y; acc[2] += f1.x; acc[3] += f1.y;
        acc[4] += f2.x; acc[5] += f2.y; acc[6] += f3.x; acc[7] += f3.y;
    }
    if (w < M) {
        uint4 sr = *(const uint4*)(SP + (size_t)w * 256 + hl * 8);
        float2 s0 = __half22float2(u2h(sr.x)), s1 = __half22float2(u2h(sr.y));
        float2 s2 = __half22float2(u2h(sr.z)), s3 = __half22float2(u2h(sr.w));
        const float inv = 1.0f / (float)FANOUT;
        __half2 o0 = __floats2half2_rn(fmaxf(fmaf(acc[0], inv, s0.x), 0.f),
                                       fmaxf(fmaf(acc[1], inv, s0.y), 0.f));
        __half2 o1 = __floats2half2_rn(fmaxf(fmaf(acc[2], inv, s1.x), 0.f),
                                       fmaxf(fmaf(acc[3], inv, s1.y), 0.f));
        __half2 o2 = __floats2half2_rn(fmaxf(fmaf(acc[4], inv, s2.x), 0.f),
                                       fmaxf(fmaf(acc[5], inv, s2.y), 0.f));
        __half2 o3 = __floats2half2_rn(fmaxf(fmaf(acc[6], inv, s3.x), 0.f),
                                       fmaxf(fmaf(acc[7], inv, s3.y), 0.f));
        uint4 o = make_uint4(*(uint32_t*)&o0, *(uint32_t*)&o1,
                             *(uint32_t*)&o2, *(uint32_t*)&o3);
        *(uint4*)(H + (size_t)w * 128 + hl * 8) = o;
    }
}

// agg_final (L4): SP fp16 [M,128] (S=cols 0-63, P=64-127), fp32 out via nodes
__global__ void agg_final(const __half* __restrict__ SP, const int* __restrict__ neigh,
                          const int* __restrict__ nodes, float* __restrict__ out, int M) {
    const int warp = (blockIdx.x * blockDim.x + threadIdx.x) >> 5;
    const int lane = threadIdx.x & 31;
    const int half = lane >> 4;
    const int hl   = lane & 15;
    const int w    = warp * 2 + half;
    const int wr   = (w < M) ? w : (M - 1);

    const int node = nodes[wr];
    const int nid  = neigh[(size_t)node * FANOUT + hl];

    float acc[4] = {};
    #pragma unroll
    for (int p = 0; p < 8; p++) {
        int nj0 = __shfl_sync(0xffffffffu, nid, half * 16 + p);
        int nj1 = __shfl_sync(0xffffffffu, nid, half * 16 + p + 8);
        uint2 a = *(const uint2*)(SP + (size_t)nj0 * 128 + 64 + hl * 4);
        uint2 b = *(const uint2*)(SP + (size_t)nj1 * 128 + 64 + hl * 4);
        __half2 s0 = __hadd2(u2h(a.x), u2h(b.x));
        __half2 s1 = __hadd2(u2h(a.y), u2h(b.y));
        float2 f0 = __half22float2(s0), f1 = __half22float2(s1);
        acc[0] += f0.x; acc[1] += f0.y; acc[2] += f1.x; acc[3] += f1.y;
    }
    if (w < M) {
        uint2 sr = *(const uint2*)(SP + (size_t)node * 128 + hl * 4);
        float2 s0 = __half22float2(u2h(sr.x)), s1 = __half22float2(u2h(sr.y));
        const float inv = 1.0f / (float)FANOUT;
        float4 r;
        r.x = fmaxf(fmaf(acc[0], inv, s0.x), 0.f);
        r.y = fmaxf(fmaf(acc[1], inv, s0.y), 0.f);
        r.z = fmaxf(fmaf(acc[2], inv, s1.x), 0.f);
        r.w = fmaxf(fmaf(acc[3], inv, s1.y), 0.f);
        *(float4*)(out + (size_t)w * 64 + hl * 4) = r;
    }
}

// ---------------------------------------------------------------------------

extern "C" void kernel_launch(void* const* d_in, const int* in_sizes, int n_in,
                              void* d_out, int out_size) {
    const float* features = (const float*)d_in[0];
    const float* W1       = (const float*)d_in[1];
    const float* W2       = (const float*)d_in[2];
    const float* W3       = (const float*)d_in[3];
    const float* W4       = (const float*)d_in[4];
    const int*   nodes    = (const int*)d_in[5];
    const int*   neigh    = (const int*)d_in[6];
    float*       out      = (float*)d_out;

    const int M = in_sizes[5];

    __half *sp, *ah, *hm, *bw;
    cudaGetSymbolAddress((void**)&sp, g_SP);
    cudaGetSymbolAddress((void**)&ah, g_Ah);
    cudaGetSymbolAddress((void**)&hm, g_Hm);
    cudaGetSymbolAddress((void**)&bw, g_Bw);

    constexpr int SMEM = 3 * 2 * 128 * 128 + 128;
    cudaFuncSetAttribute(gemm_mma<256, 256, false, false>,
                         cudaFuncAttributeMaxDynamicSharedMemorySize, SMEM);
    cudaFuncSetAttribute(gemm_mma<256, 128, true, true>,
                         cudaFuncAttributeMaxDynamicSharedMemorySize, SMEM);
    cudaFuncSetAttribute(gemm_mma<128, 128, false, false>,
                         cudaFuncAttributeMaxDynamicSharedMemorySize, SMEM);

    conv_w_all<<<(WTOT + 255) / 256, 256>>>(W1, W2, W3, W4, bw);
    conv_feat<<<(M * 64 + 255) / 256, 256>>>(features, ah, M * 64);

    const int gg  = (M + 127) / 128;
    const int ab2 = (M + 15) / 16;    // 2 rows/warp, 8 warps/block

    // Layer 1: project-first (SP = [S|P]), then combine+relu
    gemm_mma<256, 256, false, false><<<dim3(gg, 2), 256, SMEM>>>(
        ah, nullptr, bw + WOFF1, sp, M);
    agg_split<<<ab2, 256>>>(sp, neigh, ah, M);           // h1 -> g_Ah (stride 128)

    // Layer 2: gather-first, relu fused in GEMM
    mean_h<<<ab2, 256>>>(ah, neigh, hm, M);
    gemm_mma<256, 128, true, true><<<dim3(gg, 1), 256, SMEM>>>(
        ah, hm, bw + WOFF2, sp, M);                      // h2 -> g_SP (stride 128)

    // Layer 3
    mean_h<<<ab2, 256>>>(sp, neigh, hm, M);
    gemm_mma<256, 128, true, true><<<dim3(gg, 1), 256, SMEM>>>(
        sp, hm, bw + WOFF3, ah, M);                      // h3 -> g_Ah

    // Layer 4: project-first (SP4 = [S|P], 128 cols), then combine+relu via nodes
    gemm_mma<128, 128, false, false><<<dim3(gg, 1), 256, SMEM>>>(
        ah, nullptr, bw + WOFF4, sp, M);
    agg_final<<<ab2, 256>>>(sp, neigh, nodes, out, M);
}